// round 4
// baseline (speedup 1.0000x reference)
#include <cuda_runtime.h>

typedef unsigned long long u64;
typedef unsigned u32;
#define DI __device__ __forceinline__

// ---------------- weights in constant bank (uniform datapath) -------------
__constant__ float cW1[16];   // [8,2]
__constant__ float cB1[8];
__constant__ float cW2[32];   // [4,8]
__constant__ float cB2[4];
__constant__ float cW3[8];    // [2,4]

// ---------- packed f32x2 helpers (FFMA2 is PTX-only on sm_103a) ----------
DI u64 pack2(float lo, float hi) {
    u64 r;
    asm("mov.b64 %0, {%1, %2};"
        : "=l"(r) : "r"(__float_as_uint(lo)), "r"(__float_as_uint(hi)));
    return r;
}
DI void unpack2(u64 v, u32& lo, u32& hi) {
    asm("mov.b64 {%0, %1}, %2;" : "=r"(lo), "=r"(hi) : "l"(v));
}
DI u64 fma2(u64 a, u64 b, u64 c) {
    u64 d;
    asm("fma.rn.f32x2 %0, %1, %2, %3;" : "=l"(d) : "l"(a), "l"(b), "l"(c));
    return d;
}
DI u32 prmt(u32 a, u32 b, u32 sel) {
    u32 d;
    asm("prmt.b32 %0, %1, %2, %3;" : "=r"(d) : "r"(a), "r"(b), "r"(sel));
    return d;
}
// sign bytes of 4 floats -> one reg [sA,sB,sC,sD] (0xFF if negative)
DI u32 sgn4(u32 a, u32 b, u32 c, u32 d) {
    const u32 ab = prmt(a, b, 0xFBFB);   // sign-replicate a.b3, b.b3
    const u32 cd = prmt(c, d, 0xFBFB);
    return prmt(ab, cd, 0x5410);
}
DI u32 dp4a(u32 a, u32 b, u32 c) {
    u32 d;
    asm("dp4a.u32.u32 %0, %1, %2, %3;" : "=r"(d) : "r"(a), "r"(b), "r"(c));
    return d;
}

struct Wgt {
    u64 w1x[8], w1y[8], B1[8];   // (w,w) duplicated across the two positions
    u64 w2p[4][8], B2[4];
};

// weight source: true -> constant bank, false -> global pointers
template <bool C>
struct Src {
    const float *W1, *b1, *W2, *b2, *W3;
    DI float w1(int i) const { return C ? cW1[i] : __ldg(&W1[i]); }
    DI float g1(int i) const { return C ? cB1[i] : __ldg(&b1[i]); }
    DI float w2(int i) const { return C ? cW2[i] : __ldg(&W2[i]); }
    DI float g2(int i) const { return C ? cB2[i] : __ldg(&b2[i]); }
    DI float w3(int i) const { return C ? cW3[i] : __ldg(&W3[i]); }
};

// Evaluate two positions (one float4) -> two forces, via forward signs +
// 4096-entry force table (byte-offset indexed: entry e at offset 8e).
DI float4 eval(const float4 p, const Wgt& W, const char* __restrict__ tab) {
    const u64 PX = pack2(p.x, p.z);
    const u64 PY = pack2(p.y, p.w);

    u64 h1[8];
    u32 zl[8], zh[8];
#pragma unroll
    for (int i = 0; i < 8; i++) {
        const u64 z = fma2(W.w1x[i], PX, fma2(W.w1y[i], PY, W.B1[i]));
        unpack2(z, zl[i], zh[i]);
        h1[i] = pack2(fmaxf(__uint_as_float(zl[i]), 0.f),
                      fmaxf(__uint_as_float(zh[i]), 0.f));
    }
    u32 al[4], ah[4];
#pragma unroll
    for (int j = 0; j < 4; j++) {
        u64 acc = W.B2[j];
#pragma unroll
        for (int i = 0; i < 8; i++) acc = fma2(W.w2p[j][i], h1[i], acc);
        u32 sl, sh;
        unpack2(acc, sl, sh);
        al[j] = __float_as_uint(__uint_as_float(sl));   // z2 per lane needs
        ah[j] = __float_as_uint(__uint_as_float(sh));   // lo+hi? no: lanes are
    }                                                    // the two positions.

    // sign gathering: PRMT byte-masks -> DP4A bit packing (tree, no chains)
    const u32 K = 0x40201008u;        // byte weights 8,16,32,64
    const u32 ONES = 0x01010101u;

    const u32 sl_a = sgn4(zl[0], zl[1], zl[2], zl[3]);
    const u32 sl_b = sgn4(zl[4], zl[5], zl[6], zl[7]);
    const u32 sl_c = sgn4(al[0], al[1], al[2], al[3]);
    const u32 ilo = dp4a(sl_a & K, ONES, 0) |
                    (dp4a(sl_b & K, ONES, 0) << 4) |
                    (dp4a(sl_c & K, ONES, 0) << 8);

    const u32 sh_a = sgn4(zh[0], zh[1], zh[2], zh[3]);
    const u32 sh_b = sgn4(zh[4], zh[5], zh[6], zh[7]);
    const u32 sh_c = sgn4(ah[0], ah[1], ah[2], ah[3]);
    const u32 ihi = dp4a(sh_a & K, ONES, 0) |
                    (dp4a(sh_b & K, ONES, 0) << 4) |
                    (dp4a(sh_c & K, ONES, 0) << 8);

    const float2 flo = *(const float2*)(tab + ilo);
    const float2 fhi = *(const float2*)(tab + ihi);
    return make_float4(flo.x, flo.y, fhi.x, fhi.y);
}

template <bool C>
__global__ void __launch_bounds__(128, 4) toy_force_kernel(
    const float4* __restrict__ pos,
    const float*  __restrict__ gW1, const float* __restrict__ gb1,
    const float*  __restrict__ gW2, const float* __restrict__ gb2,
    const float*  __restrict__ gW3,
    float4*       __restrict__ out,
    int npairs)
{
    __shared__ float  u_s[16][8];    // u(m2)_i = sum_{j active} (-v3_j) W2[j][i]
    __shared__ float2 ftab[4096];    // force per 12-bit (m1,m2) sign pattern

    Src<C> S{gW1, gb1, gW2, gb2, gW3};
    const int tid = threadIdx.x;

    // ---- u table: one (m2, i) per thread ----
    {
        const int i = tid & 7, m = tid >> 3;
        float s = 0.f;
#pragma unroll
        for (int j = 0; j < 4; j++) {
            const float v3n = -(S.w3(j) + S.w3(4 + j));   // fold -grad into v3
            if (!((m >> j) & 1)) s += v3n * S.w2(8 * j + i);
        }
        u_s[m][i] = s;
    }
    __syncthreads();

    // ---- 4096-entry force table ----
    for (int e = tid; e < 4096; e += blockDim.x) {
        const int m2 = e >> 8;
        float fx = 0.f, fy = 0.f;
#pragma unroll
        for (int i = 0; i < 8; i++) {
            const float msk = ((e >> i) & 1) ? 0.f : 1.f;
            const float ui = msk * u_s[m2][i];
            fx = fmaf(ui, S.w1(2 * i), fx);
            fy = fmaf(ui, S.w1(2 * i + 1), fy);
        }
        ftab[e] = make_float2(fx, fy);
    }

    // ---- packed weights (positions share weights -> (w,w) duplication) ----
    Wgt W;
#pragma unroll
    for (int i = 0; i < 8; i++) {
        const float a = S.w1(2 * i), b = S.w1(2 * i + 1), c = S.g1(i);
        W.w1x[i] = pack2(a, a);
        W.w1y[i] = pack2(b, b);
        W.B1[i]  = pack2(c, c);
    }
#pragma unroll
    for (int j = 0; j < 4; j++) {
#pragma unroll
        for (int i = 0; i < 8; i++) {
            const float w = S.w2(8 * j + i);
            W.w2p[j][i] = pack2(w, w);
        }
        const float bb = S.g2(j);
        W.B2[j] = pack2(bb, bb);
    }
    __syncthreads();

    const char* tab = (const char*)ftab;
    const int stride = gridDim.x * blockDim.x;

    // ---- grid-stride, ILP=2, rotating double prefetch (round-2 winner) ----
    int ka = blockIdx.x * blockDim.x + tid;
    if (ka >= npairs) return;
    int kb = ka + stride;
    bool hb = kb < npairs;

    float4 pa = pos[ka];
    float4 pb = hb ? pos[kb] : pa;

    for (;;) {
        const int kan = ka + 2 * stride;
        const int kbn = kb + 2 * stride;
        const bool han = kan < npairs;
        const bool hbn = hb && (kbn < npairs);
        float4 na, nb;
        if (han) na = pos[kan];
        if (hbn) nb = pos[kbn];

        out[ka] = eval(pa, W, tab);
        if (hb) out[kb] = eval(pb, W, tab);

        if (!han) break;
        pa = na;
        pb = hbn ? nb : na;
        ka = kan;
        kb = kbn;
        hb = hbn;
    }
}

extern "C" void kernel_launch(void* const* d_in, const int* in_sizes, int n_in,
                              void* d_out, int out_size) {
    const float* pos = (const float*)d_in[0];
    const float* W1  = (const float*)d_in[1];
    const float* b1  = (const float*)d_in[2];
    const float* W2  = (const float*)d_in[3];
    const float* b2  = (const float*)d_in[4];
    const float* W3  = (const float*)d_in[5];
    float* out = (float*)d_out;

    const int npairs = in_sizes[0] / 4;

    // Stage weights into constant bank (D2D memcpy nodes; graph-capturable).
    bool ok = true;
    ok &= cudaMemcpyToSymbolAsync(cW1, W1, 16 * 4, 0, cudaMemcpyDeviceToDevice, 0) == cudaSuccess;
    ok &= cudaMemcpyToSymbolAsync(cB1, b1,  8 * 4, 0, cudaMemcpyDeviceToDevice, 0) == cudaSuccess;
    ok &= cudaMemcpyToSymbolAsync(cW2, W2, 32 * 4, 0, cudaMemcpyDeviceToDevice, 0) == cudaSuccess;
    ok &= cudaMemcpyToSymbolAsync(cB2, b2,  4 * 4, 0, cudaMemcpyDeviceToDevice, 0) == cudaSuccess;
    ok &= cudaMemcpyToSymbolAsync(cW3, W3,  8 * 4, 0, cudaMemcpyDeviceToDevice, 0) == cudaSuccess;

    const int threads = 128;
    const int blocks  = 592;   // 148 SMs x 4 CTAs
    if (ok) {
        toy_force_kernel<true><<<blocks, threads>>>(
            (const float4*)pos, W1, b1, W2, b2, W3, (float4*)out, npairs);
    } else {
        toy_force_kernel<false><<<blocks, threads>>>(
            (const float4*)pos, W1, b1, W2, b2, W3, (float4*)out, npairs);
    }
}